// round 16
// baseline (speedup 1.0000x reference)
#include <cuda_runtime.h>
#include <cuda_fp16.h>
#include <math.h>
#include <stdint.h>

#define NODE   30000
#define NPAD   30080          // 235 * 128
#define HID    128
#define NE     600000
#define NBATCH 4096
#define AROWS  8192
#define BN     128
#define NCHUNK 235            // NPAD/BN
#define NBM    64             // AROWS/128
#define TOTW   (NBM * NCHUNK) // 15040
#define GRID_MMA 296          // 2 CTAs per SM
#define GAMMA_F 3.0f
#define LAMB_F  30.0f
#define TAU_F   10.0f

// ---------------- device globals ----------------
__device__ float  g_feat[(size_t)NPAD * HID];    // raw aggregated (unnormalized) fp32
__device__ __half g_featH[(size_t)NPAD * HID];   // normalized fp16 (7.7MB, L2-resident)
__device__ float  g_deg[NODE];
__device__ float  g_sqn[NPAD];
__device__ float  g_pos[NBATCH];
__device__ __half g_Y[(size_t)AROWS * NPAD];     // unmasked y = 2*dot - sqn_j, fp16
__device__ float  g_rsum[AROWS], g_rsum2[AROWS];
__device__ unsigned g_rmaxU[AROWS];
__device__ double g_acc;
__device__ int    g_tp64, g_adj64;

__device__ __forceinline__ int readIdx(const void* p, long long i, int is64) {
    if (is64) return (int)((const long long*)p)[i];
    return ((const int*)p)[i];
}
__device__ __forceinline__ uint32_t smem_u32(const void* p) {
    uint32_t a;
    asm("{ .reg .u64 t; cvta.to.shared.u64 t, %1; cvt.u32.u64 %0, t; }" : "=r"(a) : "l"(p));
    return a;
}
__device__ __forceinline__ void cp_async16(uint32_t s, const void* g) {
    asm volatile("cp.async.cg.shared.global [%0], [%1], 16;" :: "r"(s), "l"(g));
}
__device__ __forceinline__ void cp_commit() {
    asm volatile("cp.async.commit_group;" ::: "memory");
}
__device__ __forceinline__ void ldsm4(uint32_t* r, uint32_t addr) {
    asm volatile("ldmatrix.sync.aligned.m8n8.x4.shared.b16 {%0,%1,%2,%3}, [%4];"
        : "=r"(r[0]), "=r"(r[1]), "=r"(r[2]), "=r"(r[3]) : "r"(addr));
}
__device__ __forceinline__ void stsm4(uint32_t addr, const uint32_t* r) {
    asm volatile("stmatrix.sync.aligned.m8n8.x4.shared.b16 [%0], {%1,%2,%3,%4};"
        :: "r"(addr), "r"(r[0]), "r"(r[1]), "r"(r[2]), "r"(r[3]) : "memory");
}
// f16 x f16 -> f16 accumulate
__device__ __forceinline__ void mma_f16(uint32_t* d, const uint32_t* a, const uint32_t* b) {
    asm volatile(
        "mma.sync.aligned.m16n8k16.row.col.f16.f16.f16.f16 "
        "{%0,%1}, {%2,%3,%4,%5}, {%6,%7}, {%0,%1};"
        : "+r"(d[0]), "+r"(d[1])
        : "r"(a[0]), "r"(a[1]), "r"(a[2]), "r"(a[3]), "r"(b[0]), "r"(b[1]));
}
// streaming store (evict-first): keeps featH resident in L2
__device__ __forceinline__ void stg_cs16(void* p, uint4 v) {
    asm volatile("st.global.cs.v4.u32 [%0], {%1,%2,%3,%4};"
        :: "l"(p), "r"(v.x), "r"(v.y), "r"(v.z), "r"(v.w) : "memory");
}
__device__ __forceinline__ unsigned encf(float f) {
    unsigned u = __float_as_uint(f);
    return (u & 0x80000000u) ? ~u : (u | 0x80000000u);
}
__device__ __forceinline__ float decf(unsigned e) {
    return (e & 0x80000000u) ? __uint_as_float(e & 0x7FFFFFFFu) : __uint_as_float(~e);
}

// ---------------- launch 0: zero + dtype detect ----------------
__global__ void k_zero(const void* tp, const void* adj) {
    size_t i = (size_t)blockIdx.x * blockDim.x + threadIdx.x;
    size_t stride = (size_t)gridDim.x * blockDim.x;
    float4 z = make_float4(0.f, 0.f, 0.f, 0.f);
    float4* f4 = (float4*)g_feat;
    size_t n4 = (size_t)NPAD * HID / 4;
    for (size_t j = i; j < n4; j += stride) f4[j] = z;
    for (size_t j = i; j < NODE; j += stride) g_deg[j] = 0.f;
    for (size_t j = i; j < AROWS; j += stride) {
        g_rsum[j] = 0.f; g_rsum2[j] = 0.f; g_rmaxU[j] = encf(-3.0e38f);
    }
    if (i == 0) {
        g_acc = 0.0;
        const int* a = (const int*)tp;
        int all0 = 1;
        for (int k = 0; k < 16; k++) if (a[2 * k + 1] != 0) all0 = 0;
        g_tp64 = all0;
        const int* b = (const int*)adj;
        all0 = 1;
        for (int k = 0; k < 16; k++) if (b[2 * k + 1] != 0) all0 = 0;
        g_adj64 = all0;
    }
}

// ---------------- launch 1: scatter raw emb + degree ----------------
__global__ void k_scatter(const void* adj, const float* emb) {
    long long idx = (long long)blockIdx.x * blockDim.x + threadIdx.x;
    if (idx >= (long long)NE * 32) return;
    int e = (int)(idx >> 5);
    int lane = (int)(idx & 31);
    int is64 = g_adj64;
    int r = readIdx(adj, e, is64);
    int c = readIdx(adj, (long long)NE + e, is64);
    if (lane == 0) atomicAdd(&g_deg[r], 1.0f);
    float4 v = ((const float4*)emb)[(size_t)c * 32 + lane];
    atomicAdd(((float4*)g_feat) + (size_t)r * 32 + lane, v);
}

__device__ __forceinline__ float warpSum(float v) {
    for (int o = 16; o; o >>= 1) v += __shfl_xor_sync(0xffffffffu, v, o);
    return v;
}

// ---------------- launch 2: normalize -> fp16, sqn, pos ----------------
__global__ __launch_bounds__(256) void k_prep(const void* tp) {
    const int tid = threadIdx.x, lane = tid & 31, w = tid >> 5;
    const int blk = blockIdx.x;
    if (blk < NPAD / 8) {
        int row = blk * 8 + w;
        float4 v = ((const float4*)g_feat)[(size_t)row * 32 + lane];
        float wgt = 1.0f;
        if (row < NODE) {
            float d = g_deg[row];
            wgt = (d > 0.f) ? (1.0f / d) : 1.0f;
        }
        float x0 = v.x * wgt, x1 = v.y * wgt, x2 = v.z * wgt, x3 = v.w * wgt;
        float s = x0 * x0 + x1 * x1 + x2 * x2 + x3 * x3;
        float stot = warpSum(s);
        if (lane == 0) g_sqn[row] = stot;
        __half2 p0 = __floats2half2_rn(x0, x1);
        __half2 p1 = __floats2half2_rn(x2, x3);
        uint2 u;
        u.x = *(uint32_t*)&p0;
        u.y = *(uint32_t*)&p1;
        ((uint2*)(g_featH + (size_t)row * HID))[lane] = u;
    } else {
        int pr = (blk - NPAD / 8) * 8 + w;
        int is64 = g_tp64;
        int l = readIdx(tp, 2LL * pr, is64);
        int r = readIdx(tp, 2LL * pr + 1, is64);
        float dl = g_deg[l], dr = g_deg[r];
        float wl = (dl > 0.f) ? (1.0f / dl) : 1.0f;
        float wr = (dr > 0.f) ? (1.0f / dr) : 1.0f;
        float4 a = ((const float4*)g_feat)[(size_t)l * 32 + lane];
        float4 b = ((const float4*)g_feat)[(size_t)r * 32 + lane];
        float dx = wl * a.x - wr * b.x, dy = wl * a.y - wr * b.y;
        float dz = wl * a.z - wr * b.z, dw = wl * a.w - wr * b.w;
        float s = warpSum(dx * dx + dy * dy + dz * dz + dw * dw);
        if (lane == 0) g_pos[pr] = s;
    }
}

// ---------------- launch 3: persistent f16 GEMM, 2 CTAs/SM ping-pong -----
// 296 CTAs x 256 threads (8 warps, 2m x 4n, warp tile 64x32): 16 warps/SM to
// hide LDSM->HMMA latency (R15 was latency-bound, no pipe >47%). Keeps the
// R15 winning structure: early prefetch (wait_group 1), stmatrix staging of Y
// through the dead B buffer, coalesced .cs copy-out, analytic mask in k_lse.
__global__ __launch_bounds__(256, 2) void k_mma(const void* tp) {
    extern __shared__ char dsm[];
    char* pA = dsm;                                // 32KB
    char* pB[2] = { dsm + 32768, dsm + 65536 };    // 2 x 32KB
    __shared__ float s_sqnj[2][BN];

    const int tid = threadIdx.x;
    const int lane = tid & 31, warp = tid >> 5;
    const int wm = warp >> 2, wn = warp & 3;       // 2m x 4n
    const int qrow = lane >> 2, qcol = lane & 3;
    const int is64 = g_tp64;
    const uint32_t sAaddr = smem_u32(pA);
    const uint32_t sBaddr[2] = { smem_u32(pB[0]), smem_u32(pB[1]) };
    const uint32_t sqnjaddr = smem_u32(s_sqnj);

    // ldmatrix lane address components
    const int aRow0 = wm * 64 + (lane & 15);       // + mi*16
    const int aKh   = (lane >> 4) & 1;
    const int bRowL = (lane & 7) + (((lane >> 4) & 1) << 3);   // + wn*32 + nt*16
    const int bKh   = (lane >> 3) & 1;

    // stmatrix lane address components
    const int stT = lane >> 3, stL = lane & 7;
    const int stRowBase = wm * 64 + ((stT & 1) << 3) + stL;    // + mi*16
    const int stCcBase  = wn * 4 + (stT >> 1);                 // + np*2 ; swizzle ^ stL

    const long long t0 = ((long long)blockIdx.x * TOTW) / GRID_MMA;
    const long long t1 = ((long long)(blockIdx.x + 1) * TOTW) / GRID_MMA;
    if (t0 >= t1) return;

    int cur_bm = -1;
    float psum[8], psum2[8], pmax[8];
#pragma unroll
    for (int s = 0; s < 8; s++) { psum[s] = 0.f; psum2[s] = 0.f; pmax[s] = -3.0e38f; }

    // prefetch B + sqn for first work item
    {
        int nb = (int)(t0 % NCHUNK) * BN;
#pragma unroll
        for (int q = 0; q < 8; q++) {
            int idx = tid + q * 256;               // 0..2047
            int row = idx >> 4, cc = idx & 15;
            cp_async16(sBaddr[0] + row * 256 + ((cc ^ (row & 7)) << 4),
                       g_featH + (size_t)(nb + row) * HID + cc * 8);
        }
        if (tid < 32) cp_async16(sqnjaddr + tid * 16, &g_sqn[nb + tid * 4]);
        cp_commit();
    }

    for (long long t = t0; t < t1; t++) {
        const int b = (int)((t - t0) & 1);
        const int bm = (int)(t / NCHUNK);
        const int ch = (int)(t % NCHUNK);

        if (bm != cur_bm) {
            if (cur_bm >= 0) {   // flush stats of previous bm
#pragma unroll
                for (int s = 0; s < 8; s++) {
                    float v = psum[s], v2 = psum2[s], m = pmax[s];
                    v += __shfl_xor_sync(0xffffffffu, v, 1);
                    v += __shfl_xor_sync(0xffffffffu, v, 2);
                    v2 += __shfl_xor_sync(0xffffffffu, v2, 1);
                    v2 += __shfl_xor_sync(0xffffffffu, v2, 2);
                    m = fmaxf(m, __shfl_xor_sync(0xffffffffu, m, 1));
                    m = fmaxf(m, __shfl_xor_sync(0xffffffffu, m, 2));
                    if (qcol == 0) {
                        int grow = cur_bm * 128 + wm * 64 + (s >> 1) * 16 + qrow + 8 * (s & 1);
                        atomicAdd(&g_rsum[grow], v);
                        atomicAdd(&g_rsum2[grow], v2);
                        atomicMax(&g_rmaxU[grow], encf(m));
                    }
                    psum[s] = 0.f; psum2[s] = 0.f; pmax[s] = -3.0e38f;
                }
            }
            // A tile: 128 gathered rows, fp16, swizzled; 2048 chunks of 16B
#pragma unroll
            for (int q = 0; q < 8; q++) {
                int idx = tid + q * 256;
                int row = idx >> 4, cc = idx & 15;
                int g = bm * 128 + row;
                int pair = g >> 1, side = g & 1;
                int arow = readIdx(tp, 2LL * pair + side, is64);
                cp_async16(sAaddr + row * 256 + ((cc ^ (row & 7)) << 4),
                           g_featH + (size_t)arow * HID + cc * 8);
            }
            cp_commit();
            cur_bm = bm;
        }

        // prefetch next B (EARLY — overlaps this chunk's MMA via wait_group 1)
        if (t + 1 < t1) {
            int nb = (int)((t + 1) % NCHUNK) * BN;
            uint32_t dst = sBaddr[b ^ 1];
#pragma unroll
            for (int q = 0; q < 8; q++) {
                int idx = tid + q * 256;
                int row = idx >> 4, cc = idx & 15;
                cp_async16(dst + row * 256 + ((cc ^ (row & 7)) << 4),
                           g_featH + (size_t)(nb + row) * HID + cc * 8);
            }
            if (tid < 32) cp_async16(sqnjaddr + (b ^ 1) * (BN * 4) + tid * 16, &g_sqn[nb + tid * 4]);
            cp_commit();
            asm volatile("cp.async.wait_group 1;" ::: "memory");
        } else {
            asm volatile("cp.async.wait_group 0;" ::: "memory");
        }
        __syncthreads();                           // (1) tile b ready

        // ---- compute 128x128 chunk: 8 kgroups x (6 LDSM.x4 + 16 HMMA f16) ----
        uint32_t acc[4][4][2];
#pragma unroll
        for (int mi = 0; mi < 4; mi++)
#pragma unroll
            for (int ni = 0; ni < 4; ni++) { acc[mi][ni][0] = 0u; acc[mi][ni][1] = 0u; }

        const uint32_t sB = sBaddr[b];
#pragma unroll
        for (int kg = 0; kg < 8; kg++) {
            uint32_t af[4][4], bf[2][4];
            const int kcA = 2 * kg + aKh;
            const int kcB = 2 * kg + bKh;
#pragma unroll
            for (int mi = 0; mi < 4; mi++) {
                int row = aRow0 + mi * 16;
                ldsm4(af[mi], sAaddr + row * 256 + ((kcA ^ (row & 7)) << 4));
            }
#pragma unroll
            for (int nt = 0; nt < 2; nt++) {
                int row = wn * 32 + nt * 16 + bRowL;
                ldsm4(bf[nt], sB + row * 256 + ((kcB ^ (row & 7)) << 4));
            }
#pragma unroll
            for (int mi = 0; mi < 4; mi++)
#pragma unroll
                for (int ni = 0; ni < 4; ni++) {
                    uint32_t bb[2] = { bf[ni >> 1][(ni & 1) * 2], bf[ni >> 1][(ni & 1) * 2 + 1] };
                    mma_f16(acc[mi][ni], af[mi], bb);
                }
        }

        __syncthreads();                           // (2) pB[b] fully consumed

        // ---- epilogue: y = 2*acc - sqn_j (fp32); stats; stmatrix into pB[b] ----
        const int jc = ch * BN;
#pragma unroll
        for (int mi = 0; mi < 4; mi++) {
            const int s0 = mi * 2, s1 = s0 + 1;
#pragma unroll
            for (int np = 0; np < 2; np++) {
                uint32_t hh[4];
#pragma unroll
                for (int d = 0; d < 2; d++) {
                    int ni = np * 2 + d;
                    int c = wn * 32 + ni * 8 + qcol * 2;
                    float sq0 = s_sqnj[b][c], sq1 = s_sqnj[b][c + 1];
                    float2 f0 = __half22float2(*(__half2*)&acc[mi][ni][0]);
                    float2 f1 = __half22float2(*(__half2*)&acc[mi][ni][1]);
                    float y00 = fmaf(2.f, f0.x, -sq0);
                    float y01 = fmaf(2.f, f0.y, -sq1);
                    float y10 = fmaf(2.f, f1.x, -sq0);
                    float y11 = fmaf(2.f, f1.y, -sq1);
                    __half2 a0 = __floats2half2_rn(y00, y01);
                    __half2 a1 = __floats2half2_rn(y10, y11);
                    hh[d * 2 + 0] = *(uint32_t*)&a0;
                    hh[d * 2 + 1] = *(uint32_t*)&a1;
                    if (jc + c < NODE) {
                        psum[s0] += y00 + y01;
                        psum2[s0] += y00 * y00 + y01 * y01;
                        pmax[s0] = fmaxf(pmax[s0], fmaxf(y00, y01));
                        psum[s1] += y10 + y11;
                        psum2[s1] += y10 * y10 + y11 * y11;
                        pmax[s1] = fmaxf(pmax[s1], fmaxf(y10, y11));
                    }
                }
                int rr = stRowBase + mi * 16;
                int cc = stCcBase + np * 2;
                stsm4(sB + rr * 256 + ((cc ^ stL) << 4), hh);
            }
        }

        __syncthreads();                           // (3) staging complete

        // ---- coalesced copy-out: 8 x (LDS.128 + STG.cs.128) per thread ----
#pragma unroll
        for (int q = 0; q < 8; q++) {
            int idx = tid + q * 256;
            int row = idx >> 4, cc = idx & 15;
            uint4 v;
            uint32_t a = sB + row * 256 + ((cc ^ (row & 7)) << 4);
            asm volatile("ld.shared.v4.u32 {%0,%1,%2,%3}, [%4];"
                : "=r"(v.x), "=r"(v.y), "=r"(v.z), "=r"(v.w) : "r"(a));
            stg_cs16(g_Y + (size_t)(cur_bm * 128 + row) * NPAD + jc + cc * 8, v);
        }

        __syncthreads();                           // (4) copy done before prefetch reuses pB[b]
    }

    // final flush
#pragma unroll
    for (int s = 0; s < 8; s++) {
        float v = psum[s], v2 = psum2[s], m = pmax[s];
        v += __shfl_xor_sync(0xffffffffu, v, 1);
        v += __shfl_xor_sync(0xffffffffu, v, 2);
        v2 += __shfl_xor_sync(0xffffffffu, v2, 1);
        v2 += __shfl_xor_sync(0xffffffffu, v2, 2);
        m = fmaxf(m, __shfl_xor_sync(0xffffffffu, m, 1));
        m = fmaxf(m, __shfl_xor_sync(0xffffffffu, m, 2));
        if (qcol == 0) {
            int grow = cur_bm * 128 + wm * 64 + (s >> 1) * 16 + qrow + 8 * (s & 1);
            atomicAdd(&g_rsum[grow], v);
            atomicAdd(&g_rsum2[grow], v2);
            atomicMax(&g_rmaxU[grow], encf(m));
        }
    }
}

// ---------------- launch 4: logsumexp with analytic mask correction --------
__device__ float blockSum(float v) {
    __shared__ float scr[8];
    __shared__ float bc;
    v = warpSum(v);
    if ((threadIdx.x & 31) == 0) scr[threadIdx.x >> 5] = v;
    __syncthreads();
    if (threadIdx.x < 32) {
        float t = (threadIdx.x < 8) ? scr[threadIdx.x] : 0.f;
        t = warpSum(t);
        if (threadIdx.x == 0) bc = t;
    }
    __syncthreads();
    float r = bc;
    __syncthreads();
    return r;
}

__device__ __forceinline__ void unpack8(uint4 v, float* f) {
    float2 a = __half22float2(*(__half2*)&v.x);
    float2 b = __half22float2(*(__half2*)&v.y);
    float2 c = __half22float2(*(__half2*)&v.z);
    float2 d = __half22float2(*(__half2*)&v.w);
    f[0] = a.x; f[1] = a.y; f[2] = b.x; f[3] = b.y;
    f[4] = c.x; f[5] = c.y; f[6] = d.x; f[7] = d.y;
}

__global__ __launch_bounds__(256) void k_lse(const void* tp) {
    const int row = blockIdx.x;
    const int tid = threadIdx.x;
    const int pair = row >> 1, side = row & 1;
    const int is64 = g_tp64;
    const int l = readIdx(tp, 2LL * pair, is64);
    const int r = readIdx(tp, 2LL * pair + 1, is64);
    const float pos = g_pos[pair];
    const float sqa = g_sqn[side ? r : l];
    const float cm = pos - sqa + GAMMA_F;

    // analytic unmasked values at masked columns (exact identities):
    //   a==col -> y_old = sqa ;  partner col -> y_old = sqa - pos
    float yol, yor, ynl, ynr;
    float sum = g_rsum[row], sum2 = g_rsum2[row];
    if (l != r) {
        yol = side ? (sqa - pos) : sqa;
        yor = side ? sqa : (sqa - pos);
        ynl = -cm; ynr = -cm;
        sum += (ynl - yol) + (ynr - yor);
        sum2 += (ynl * ynl - yol * yol) + (ynr * ynr - yor * yor);
    } else {
        yol = sqa;
        ynl = -yol - 2.0f * cm;       // mask = -1 when l == r
        yor = 0.f; ynr = 0.f;
        sum += ynl - yol;
        sum2 += ynl * ynl - yol * yol;
    }
    const float mean = sum * (1.0f / 30000.0f);
    const float var = sum2 * (1.0f / 30000.0f) - mean * mean;
    const float a = LAMB_F / sqrtf(var);
    const float mx = decf(g_rmaxU[row]);

    const uint4* x4 = (const uint4*)(g_Y + (size_t)row * NPAD);
    float se = 0.f;
    for (int i = tid; i < 3750; i += 256) {   // 3750*8 = 30000
        uint4 v = __ldcs(&x4[i]);             // read-once stream, evict-first
        float f[8];
        unpack8(v, f);
#pragma unroll
        for (int c = 0; c < 8; c++) se += __expf(a * (f[c] - mx));
    }
    float setot = blockSum(se);
    if (tid == 0) {
        setot += __expf(a * (ynl - mx)) - __expf(a * (yol - mx));
        if (l != r) setot += __expf(a * (ynr - mx)) - __expf(a * (yor - mx));
        float lse = a * (mx - mean) + TAU_F + logf(setot);
        atomicAdd(&g_acc, (double)lse);
    }
}

__global__ void k_final(float* out) {
    if (threadIdx.x == 0 && blockIdx.x == 0)
        out[0] = (float)(g_acc / (double)NBATCH);
}

// ---------------- launch ----------------
extern "C" void kernel_launch(void* const* d_in, const int* in_sizes, int n_in,
                              void* d_out, int out_size) {
    const void* tp = nullptr;
    const void* adj = nullptr;
    const float* emb = nullptr;
    for (int i = 0; i < n_in; i++) {
        if (in_sizes[i] == NBATCH * 2)        tp  = d_in[i];
        else if (in_sizes[i] == 2 * NE)       adj = d_in[i];
        else if (in_sizes[i] == NODE * HID)   emb = (const float*)d_in[i];
    }
    float* out = (float*)d_out;

    k_zero<<<2048, 256>>>(tp, adj);                                        // idx 0
    k_scatter<<<(int)(((long long)NE * 32 + 255) / 256), 256>>>(adj, emb); // idx 1
    k_prep<<<NPAD / 8 + NBATCH / 8, 256>>>(tp);                            // idx 2

    // dynamic smem: A 32KB + 2 x B 32KB = 96KB per CTA (2 CTAs/SM)
    cudaFuncSetAttribute(k_mma, cudaFuncAttributeMaxDynamicSharedMemorySize, 98304);
    k_mma<<<GRID_MMA, 256, 98304>>>(tp);                                   // idx 3 (ncu)

    k_lse<<<AROWS, 256>>>(tp);                                             // idx 4
    k_final<<<1, 1>>>(out);                                                // idx 5
}

// round 17
// speedup vs baseline: 1.1390x; 1.1390x over previous
#include <cuda_runtime.h>
#include <cuda_fp16.h>
#include <math.h>
#include <stdint.h>

#define NODE   30000
#define NPAD   30080          // 235 * 128
#define HID    128
#define NE     600000
#define NBATCH 4096
#define AROWS  8192
#define BN     128
#define NCHUNK 235            // NPAD/BN
#define NBM    64             // AROWS/128
#define TOTW   (NBM * NCHUNK) // 15040
#define GRID_MMA 296          // 2 CTAs per SM
#define GAMMA_F 3.0f
#define LAMB_F  30.0f
#define TAU_F   10.0f

// ---------------- device globals ----------------
__device__ float  g_feat[(size_t)NPAD * HID];    // raw aggregated (unnormalized) fp32
__device__ __half g_featH[(size_t)NPAD * HID];   // normalized fp16 (7.7MB, L2-resident)
__device__ float  g_deg[NODE];
__device__ float  g_sqn[NPAD];
__device__ float  g_pos[NBATCH];
__device__ uint4  g_Yb[(size_t)TOTW * 2048];     // 493MB: y in fragment-blocked layout
__device__ float  g_rsum[AROWS], g_rsum2[AROWS];
__device__ unsigned g_rmaxU[AROWS];
__device__ float  g_a[AROWS], g_amx[AROWS], g_base[AROWS], g_secorr[AROWS], g_se[AROWS];
__device__ double g_acc;
__device__ int    g_tp64, g_adj64;

__device__ __forceinline__ int readIdx(const void* p, long long i, int is64) {
    if (is64) return (int)((const long long*)p)[i];
    return ((const int*)p)[i];
}
__device__ __forceinline__ uint32_t smem_u32(const void* p) {
    uint32_t a;
    asm("{ .reg .u64 t; cvta.to.shared.u64 t, %1; cvt.u32.u64 %0, t; }" : "=r"(a) : "l"(p));
    return a;
}
__device__ __forceinline__ void cp_async16(uint32_t s, const void* g) {
    asm volatile("cp.async.cg.shared.global [%0], [%1], 16;" :: "r"(s), "l"(g));
}
__device__ __forceinline__ void cp_commit() {
    asm volatile("cp.async.commit_group;" ::: "memory");
}
__device__ __forceinline__ void ldsm4(uint32_t* r, uint32_t addr) {
    asm volatile("ldmatrix.sync.aligned.m8n8.x4.shared.b16 {%0,%1,%2,%3}, [%4];"
        : "=r"(r[0]), "=r"(r[1]), "=r"(r[2]), "=r"(r[3]) : "r"(addr));
}
// f16 x f16 -> f16 accumulate
__device__ __forceinline__ void mma_f16(uint32_t* d, const uint32_t* a, const uint32_t* b) {
    asm volatile(
        "mma.sync.aligned.m16n8k16.row.col.f16.f16.f16.f16 "
        "{%0,%1}, {%2,%3,%4,%5}, {%6,%7}, {%0,%1};"
        : "+r"(d[0]), "+r"(d[1])
        : "r"(a[0]), "r"(a[1]), "r"(a[2]), "r"(a[3]), "r"(b[0]), "r"(b[1]));
}
// streaming store (evict-first): keeps featH resident in L2
__device__ __forceinline__ void stg_cs16(void* p, uint4 v) {
    asm volatile("st.global.cs.v4.u32 [%0], {%1,%2,%3,%4};"
        :: "l"(p), "r"(v.x), "r"(v.y), "r"(v.z), "r"(v.w) : "memory");
}
__device__ __forceinline__ unsigned encf(float f) {
    unsigned u = __float_as_uint(f);
    return (u & 0x80000000u) ? ~u : (u | 0x80000000u);
}
__device__ __forceinline__ float decf(unsigned e) {
    return (e & 0x80000000u) ? __uint_as_float(e & 0x7FFFFFFFu) : __uint_as_float(~e);
}

// ---------------- launch 0: zero + dtype detect ----------------
__global__ void k_zero(const void* tp, const void* adj) {
    size_t i = (size_t)blockIdx.x * blockDim.x + threadIdx.x;
    size_t stride = (size_t)gridDim.x * blockDim.x;
    float4 z = make_float4(0.f, 0.f, 0.f, 0.f);
    float4* f4 = (float4*)g_feat;
    size_t n4 = (size_t)NPAD * HID / 4;
    for (size_t j = i; j < n4; j += stride) f4[j] = z;
    for (size_t j = i; j < NODE; j += stride) g_deg[j] = 0.f;
    for (size_t j = i; j < AROWS; j += stride) {
        g_rsum[j] = 0.f; g_rsum2[j] = 0.f; g_rmaxU[j] = encf(-3.0e38f);
        g_se[j] = 0.f;
    }
    if (i == 0) {
        g_acc = 0.0;
        const int* a = (const int*)tp;
        int all0 = 1;
        for (int k = 0; k < 16; k++) if (a[2 * k + 1] != 0) all0 = 0;
        g_tp64 = all0;
        const int* b = (const int*)adj;
        all0 = 1;
        for (int k = 0; k < 16; k++) if (b[2 * k + 1] != 0) all0 = 0;
        g_adj64 = all0;
    }
}

// ---------------- launch 1: scatter raw emb + degree ----------------
__global__ void k_scatter(const void* adj, const float* emb) {
    long long idx = (long long)blockIdx.x * blockDim.x + threadIdx.x;
    if (idx >= (long long)NE * 32) return;
    int e = (int)(idx >> 5);
    int lane = (int)(idx & 31);
    int is64 = g_adj64;
    int r = readIdx(adj, e, is64);
    int c = readIdx(adj, (long long)NE + e, is64);
    if (lane == 0) atomicAdd(&g_deg[r], 1.0f);
    float4 v = ((const float4*)emb)[(size_t)c * 32 + lane];
    atomicAdd(((float4*)g_feat) + (size_t)r * 32 + lane, v);
}

__device__ __forceinline__ float warpSum(float v) {
    for (int o = 16; o; o >>= 1) v += __shfl_xor_sync(0xffffffffu, v, o);
    return v;
}

// ---------------- launch 2: normalize -> fp16, sqn, pos ----------------
__global__ __launch_bounds__(256) void k_prep(const void* tp) {
    const int tid = threadIdx.x, lane = tid & 31, w = tid >> 5;
    const int blk = blockIdx.x;
    if (blk < NPAD / 8) {
        int row = blk * 8 + w;
        float4 v = ((const float4*)g_feat)[(size_t)row * 32 + lane];
        float wgt = 1.0f;
        if (row < NODE) {
            float d = g_deg[row];
            wgt = (d > 0.f) ? (1.0f / d) : 1.0f;
        }
        float x0 = v.x * wgt, x1 = v.y * wgt, x2 = v.z * wgt, x3 = v.w * wgt;
        float s = x0 * x0 + x1 * x1 + x2 * x2 + x3 * x3;
        float stot = warpSum(s);
        if (lane == 0) g_sqn[row] = stot;
        __half2 p0 = __floats2half2_rn(x0, x1);
        __half2 p1 = __floats2half2_rn(x2, x3);
        uint2 u;
        u.x = *(uint32_t*)&p0;
        u.y = *(uint32_t*)&p1;
        ((uint2*)(g_featH + (size_t)row * HID))[lane] = u;
    } else {
        int pr = (blk - NPAD / 8) * 8 + w;
        int is64 = g_tp64;
        int l = readIdx(tp, 2LL * pr, is64);
        int r = readIdx(tp, 2LL * pr + 1, is64);
        float dl = g_deg[l], dr = g_deg[r];
        float wl = (dl > 0.f) ? (1.0f / dl) : 1.0f;
        float wr = (dr > 0.f) ? (1.0f / dr) : 1.0f;
        float4 a = ((const float4*)g_feat)[(size_t)l * 32 + lane];
        float4 b = ((const float4*)g_feat)[(size_t)r * 32 + lane];
        float dx = wl * a.x - wr * b.x, dy = wl * a.y - wr * b.y;
        float dz = wl * a.z - wr * b.z, dw = wl * a.w - wr * b.w;
        float s = warpSum(dx * dx + dy * dy + dz * dz + dw * dw);
        if (lane == 0) g_pos[pr] = s;
    }
}

// ---------------- launch 3: persistent f16 GEMM, 2 CTAs/SM ping-pong -----
// R15 config (4 warps, warp tile 64x64, early prefetch), but the epilogue
// stores y DIRECTLY from registers into a fragment-blocked global layout
// (g_Yb[(bm*NCHUNK+ch)*2048 + q*128 + tid], coalesced 512B/warp per q) —
// no stmatrix staging, no smem copy-out, only 2 barriers per chunk.
// k_pexp mirrors this thread mapping to re-read Y coalesced.
__global__ __launch_bounds__(128, 2) void k_mma(const void* tp) {
    extern __shared__ char dsm[];
    char* pA = dsm;                                // 32KB
    char* pB[2] = { dsm + 32768, dsm + 65536 };    // 2 x 32KB
    __shared__ float s_sqnj[2][BN];

    const int tid = threadIdx.x;
    const int lane = tid & 31, warp = tid >> 5;
    const int wm = warp >> 1, wn = warp & 1;       // 2m x 2n
    const int qrow = lane >> 2, qcol = lane & 3;
    const int is64 = g_tp64;
    const uint32_t sAaddr = smem_u32(pA);
    const uint32_t sBaddr[2] = { smem_u32(pB[0]), smem_u32(pB[1]) };
    const uint32_t sqnjaddr = smem_u32(s_sqnj);

    // ldmatrix lane address components
    const int aRow0 = wm * 64 + (lane & 15);       // + mi*16
    const int aKh   = (lane >> 4) & 1;
    const int bRowL = (lane & 7) + (((lane >> 4) & 1) << 3);   // + wn*64 + nt*16
    const int bKh   = (lane >> 3) & 1;

    const long long t0 = ((long long)blockIdx.x * TOTW) / GRID_MMA;
    const long long t1 = ((long long)(blockIdx.x + 1) * TOTW) / GRID_MMA;
    if (t0 >= t1) return;

    int cur_bm = -1;
    float psum[8], psum2[8], pmax[8];
#pragma unroll
    for (int s = 0; s < 8; s++) { psum[s] = 0.f; psum2[s] = 0.f; pmax[s] = -3.0e38f; }

    // prefetch B + sqn for first work item
    {
        int nb = (int)(t0 % NCHUNK) * BN;
#pragma unroll
        for (int q = 0; q < 16; q++) {
            int idx = tid + q * 128;               // 0..2047
            int row = idx >> 4, cc = idx & 15;
            cp_async16(sBaddr[0] + row * 256 + ((cc ^ (row & 7)) << 4),
                       g_featH + (size_t)(nb + row) * HID + cc * 8);
        }
        if (tid < 32) cp_async16(sqnjaddr + tid * 16, &g_sqn[nb + tid * 4]);
        cp_commit();
    }

    for (long long t = t0; t < t1; t++) {
        const int b = (int)((t - t0) & 1);
        const int bm = (int)(t / NCHUNK);
        const int ch = (int)(t % NCHUNK);

        if (bm != cur_bm) {
            if (cur_bm >= 0) {   // flush stats of previous bm
#pragma unroll
                for (int s = 0; s < 8; s++) {
                    float v = psum[s], v2 = psum2[s], m = pmax[s];
                    v += __shfl_xor_sync(0xffffffffu, v, 1);
                    v += __shfl_xor_sync(0xffffffffu, v, 2);
                    v2 += __shfl_xor_sync(0xffffffffu, v2, 1);
                    v2 += __shfl_xor_sync(0xffffffffu, v2, 2);
                    m = fmaxf(m, __shfl_xor_sync(0xffffffffu, m, 1));
                    m = fmaxf(m, __shfl_xor_sync(0xffffffffu, m, 2));
                    if (qcol == 0) {
                        int grow = cur_bm * 128 + wm * 64 + (s >> 1) * 16 + qrow + 8 * (s & 1);
                        atomicAdd(&g_rsum[grow], v);
                        atomicAdd(&g_rsum2[grow], v2);
                        atomicMax(&g_rmaxU[grow], encf(m));
                    }
                    psum[s] = 0.f; psum2[s] = 0.f; pmax[s] = -3.0e38f;
                }
            }
            // A tile: 128 gathered rows, fp16, swizzled; 2048 chunks of 16B
#pragma unroll
            for (int q = 0; q < 16; q++) {
                int idx = tid + q * 128;
                int row = idx >> 4, cc = idx & 15;
                int g = bm * 128 + row;
                int pair = g >> 1, side = g & 1;
                int arow = readIdx(tp, 2LL * pair + side, is64);
                cp_async16(sAaddr + row * 256 + ((cc ^ (row & 7)) << 4),
                           g_featH + (size_t)arow * HID + cc * 8);
            }
            cp_commit();
            cur_bm = bm;
        }

        // prefetch next B (EARLY — overlaps this chunk's MMA via wait_group 1)
        if (t + 1 < t1) {
            int nb = (int)((t + 1) % NCHUNK) * BN;
            uint32_t dst = sBaddr[b ^ 1];
#pragma unroll
            for (int q = 0; q < 16; q++) {
                int idx = tid + q * 128;
                int row = idx >> 4, cc = idx & 15;
                cp_async16(dst + row * 256 + ((cc ^ (row & 7)) << 4),
                           g_featH + (size_t)(nb + row) * HID + cc * 8);
            }
            if (tid < 32) cp_async16(sqnjaddr + (b ^ 1) * (BN * 4) + tid * 16, &g_sqn[nb + tid * 4]);
            cp_commit();
            asm volatile("cp.async.wait_group 1;" ::: "memory");
        } else {
            asm volatile("cp.async.wait_group 0;" ::: "memory");
        }
        __syncthreads();                           // (1) tile b ready

        // ---- compute 128x128 chunk: 8 kgroups x (8 LDSM.x4 + 32 HMMA f16) ----
        uint32_t acc[4][8][2];
#pragma unroll
        for (int mi = 0; mi < 4; mi++)
#pragma unroll
            for (int ni = 0; ni < 8; ni++) { acc[mi][ni][0] = 0u; acc[mi][ni][1] = 0u; }

        const uint32_t sB = sBaddr[b];
#pragma unroll
        for (int kg = 0; kg < 8; kg++) {
            uint32_t af[4][4], bf[4][4];
            const int kcA = 2 * kg + aKh;
            const int kcB = 2 * kg + bKh;
#pragma unroll
            for (int mi = 0; mi < 4; mi++) {
                int row = aRow0 + mi * 16;
                ldsm4(af[mi], sAaddr + row * 256 + ((kcA ^ (row & 7)) << 4));
            }
#pragma unroll
            for (int nt = 0; nt < 4; nt++) {
                int row = wn * 64 + nt * 16 + bRowL;
                ldsm4(bf[nt], sB + row * 256 + ((kcB ^ (row & 7)) << 4));
            }
#pragma unroll
            for (int mi = 0; mi < 4; mi++)
#pragma unroll
                for (int ni = 0; ni < 8; ni++) {
                    uint32_t bb[2] = { bf[ni >> 1][(ni & 1) * 2], bf[ni >> 1][(ni & 1) * 2 + 1] };
                    mma_f16(acc[mi][ni], af[mi], bb);
                }
        }

        // ---- epilogue: y = 2*acc - sqn_j (fp32); stats; DIRECT blocked store ----
        const int jc = ch * BN;
        const size_t blockBase = (size_t)(bm * NCHUNK + ch) * 2048;
#pragma unroll
        for (int mi = 0; mi < 4; mi++) {
            const int s0 = mi * 2, s1 = s0 + 1;
#pragma unroll
            for (int np = 0; np < 4; np++) {
                uint32_t hh[4];
#pragma unroll
                for (int d = 0; d < 2; d++) {
                    int ni = np * 2 + d;
                    int c = wn * 64 + ni * 8 + qcol * 2;
                    float sq0 = s_sqnj[b][c], sq1 = s_sqnj[b][c + 1];
                    float2 f0 = __half22float2(*(__half2*)&acc[mi][ni][0]);
                    float2 f1 = __half22float2(*(__half2*)&acc[mi][ni][1]);
                    float y00 = fmaf(2.f, f0.x, -sq0);
                    float y01 = fmaf(2.f, f0.y, -sq1);
                    float y10 = fmaf(2.f, f1.x, -sq0);
                    float y11 = fmaf(2.f, f1.y, -sq1);
                    __half2 a0 = __floats2half2_rn(y00, y01);
                    __half2 a1 = __floats2half2_rn(y10, y11);
                    hh[d * 2 + 0] = *(uint32_t*)&a0;
                    hh[d * 2 + 1] = *(uint32_t*)&a1;
                    if (jc + c < NODE) {
                        psum[s0] += y00 + y01;
                        psum2[s0] += y00 * y00 + y01 * y01;
                        pmax[s0] = fmaxf(pmax[s0], fmaxf(y00, y01));
                        psum[s1] += y10 + y11;
                        psum2[s1] += y10 * y10 + y11 * y11;
                        pmax[s1] = fmaxf(pmax[s1], fmaxf(y10, y11));
                    }
                }
                stg_cs16(&g_Yb[blockBase + (mi * 4 + np) * 128 + tid], *(uint4*)hh);
            }
        }

        __syncthreads();   // (2) pB[b]/s_sqnj[b] consumed before next prefetch overwrites
    }

    // final flush
#pragma unroll
    for (int s = 0; s < 8; s++) {
        float v = psum[s], v2 = psum2[s], m = pmax[s];
        v += __shfl_xor_sync(0xffffffffu, v, 1);
        v += __shfl_xor_sync(0xffffffffu, v, 2);
        v2 += __shfl_xor_sync(0xffffffffu, v2, 1);
        v2 += __shfl_xor_sync(0xffffffffu, v2, 2);
        m = fmaxf(m, __shfl_xor_sync(0xffffffffu, m, 1));
        m = fmaxf(m, __shfl_xor_sync(0xffffffffu, m, 2));
        if (qcol == 0) {
            int grow = cur_bm * 128 + wm * 64 + (s >> 1) * 16 + qrow + 8 * (s & 1);
            atomicAdd(&g_rsum[grow], v);
            atomicAdd(&g_rsum2[grow], v2);
            atomicMax(&g_rmaxU[grow], encf(m));
        }
    }
}

// ---------------- launch 4: per-row corrected stats -> a, a*mx, base, corr --
__global__ __launch_bounds__(256) void k_stats2(const void* tp) {
    const int row = blockIdx.x * 256 + threadIdx.x;
    if (row >= AROWS) return;
    const int pair = row >> 1, side = row & 1;
    const int is64 = g_tp64;
    const int l = readIdx(tp, 2LL * pair, is64);
    const int r = readIdx(tp, 2LL * pair + 1, is64);
    const float pos = g_pos[pair];
    const float sqa = g_sqn[side ? r : l];
    const float cm = pos - sqa + GAMMA_F;

    float yol, yor, ynl, ynr;
    float sum = g_rsum[row], sum2 = g_rsum2[row];
    if (l != r) {
        yol = side ? (sqa - pos) : sqa;
        yor = side ? sqa : (sqa - pos);
        ynl = -cm; ynr = -cm;
        sum += (ynl - yol) + (ynr - yor);
        sum2 += (ynl * ynl - yol * yol) + (ynr * ynr - yor * yor);
    } else {
        yol = sqa;
        ynl = -yol - 2.0f * cm;       // mask = -1 when l == r
        yor = 0.f; ynr = 0.f;
        sum += ynl - yol;
        sum2 += ynl * ynl - yol * yol;
    }
    const float mean = sum * (1.0f / 30000.0f);
    const float var = sum2 * (1.0f / 30000.0f) - mean * mean;
    const float a = LAMB_F / sqrtf(var);
    const float mx = decf(g_rmaxU[row]);

    float corr = __expf(a * (ynl - mx)) - __expf(a * (yol - mx));
    if (l != r) corr += __expf(a * (ynr - mx)) - __expf(a * (yor - mx));

    g_a[row] = a;
    g_amx[row] = a * mx;
    g_base[row] = a * (mx - mean) + TAU_F;
    g_secorr[row] = corr;
}

// ---------------- launch 5: partial exp sums over blocked Y ---------------
// Mirrors k_mma's thread mapping. Grid = NBM*16 CTAs x 128 thr; CTA handles
// bm = blk>>4, chunk slice (blk&15). Coalesced uint4 ldcs; 8 row-partials.
__global__ __launch_bounds__(128) void k_pexp() {
    const int tid = threadIdx.x;
    const int lane = tid & 31, warp = tid >> 5;
    const int wm = warp >> 1;
    const int qrow = lane >> 2, qcol = lane & 3;
    const int bm = blockIdx.x >> 4, sl = blockIdx.x & 15;
    const int c0 = (NCHUNK * sl) >> 4;
    const int c1 = (NCHUNK * (sl + 1)) >> 4;

    float as[8], ams[8], se[8];
    int grow[8];
#pragma unroll
    for (int s = 0; s < 8; s++) {
        int rl = wm * 64 + (s >> 1) * 16 + qrow + 8 * (s & 1);
        grow[s] = bm * 128 + rl;
        as[s] = g_a[grow[s]];
        ams[s] = g_amx[grow[s]];
        se[s] = 0.f;
    }

    for (int ch = c0; ch < c1; ch++) {
        const size_t base = (size_t)(bm * NCHUNK + ch) * 2048;
#pragma unroll
        for (int q = 0; q < 16; q++) {
            uint4 v = __ldcs(&g_Yb[base + q * 128 + tid]);
            const int s0 = (q >> 2) * 2, s1 = s0 + 1;
            float2 f0 = __half22float2(*(__half2*)&v.x);   // rows s0
            float2 f1 = __half22float2(*(__half2*)&v.y);   // rows s1
            float2 f2 = __half22float2(*(__half2*)&v.z);   // rows s0
            float2 f3 = __half22float2(*(__half2*)&v.w);   // rows s1
            se[s0] += __expf(fmaf(as[s0], f0.x, -ams[s0])) + __expf(fmaf(as[s0], f0.y, -ams[s0]))
                    + __expf(fmaf(as[s0], f2.x, -ams[s0])) + __expf(fmaf(as[s0], f2.y, -ams[s0]));
            se[s1] += __expf(fmaf(as[s1], f1.x, -ams[s1])) + __expf(fmaf(as[s1], f1.y, -ams[s1]))
                    + __expf(fmaf(as[s1], f3.x, -ams[s1])) + __expf(fmaf(as[s1], f3.y, -ams[s1]));
        }
    }

#pragma unroll
    for (int s = 0; s < 8; s++) {
        float v = se[s];
        v += __shfl_xor_sync(0xffffffffu, v, 1);
        v += __shfl_xor_sync(0xffffffffu, v, 2);
        if (qcol == 0) atomicAdd(&g_se[grow[s]], v);
    }
}

// ---------------- launch 6: per-row lse -> g_acc --------------------------
__global__ __launch_bounds__(256) void k_fin2() {
    const int row = blockIdx.x * 256 + threadIdx.x;
    if (row >= AROWS) return;
    float lse = g_base[row] + logf(g_se[row] + g_secorr[row]);
    atomicAdd(&g_acc, (double)lse);
}

__global__ void k_final(float* out) {
    if (threadIdx.x == 0 && blockIdx.x == 0)
        out[0] = (float)(g_acc / (double)NBATCH);
}

// ---------------- launch ----------------
extern "C" void kernel_launch(void* const* d_in, const int* in_sizes, int n_in,
                              void* d_out, int out_size) {
    const void* tp = nullptr;
    const void* adj = nullptr;
    const float* emb = nullptr;
    for (int i = 0; i < n_in; i++) {
        if (in_sizes[i] == NBATCH * 2)        tp  = d_in[i];
        else if (in_sizes[i] == 2 * NE)       adj = d_in[i];
        else if (in_sizes[i] == NODE * HID)   emb = (const float*)d_in[i];
    }
    float* out = (float*)d_out;

    k_zero<<<2048, 256>>>(tp, adj);                                        // idx 0
    k_scatter<<<(int)(((long long)NE * 32 + 255) / 256), 256>>>(adj, emb); // idx 1
    k_prep<<<NPAD / 8 + NBATCH / 8, 256>>>(tp);                            // idx 2

    // dynamic smem: A 32KB + 2 x B 32KB = 96KB per CTA (2 CTAs/SM)
    cudaFuncSetAttribute(k_mma, cudaFuncAttributeMaxDynamicSharedMemorySize, 98304);
    k_mma<<<GRID_MMA, 128, 98304>>>(tp);                                   // idx 3 (ncu)

    k_stats2<<<AROWS / 256, 256>>>(tp);                                    // idx 4
    k_pexp<<<NBM * 16, 128>>>();                                           // idx 5
    k_fin2<<<AROWS / 256, 256>>>();                                        // idx 6
    k_final<<<1, 1>>>(out);                                                // idx 7
}